// round 15
// baseline (speedup 1.0000x reference)
#include <cuda_runtime.h>
#include <cuda_bf16.h>
#include <cstdint>

#define DDIM 512
#define KC   512
#define TMR  96
#define NROWS 131072

// smem layout (bytes)
#define OFF_ZS  0         // 96 rows x 1024B bf16, swizzled
#define OFF_PS  98304     // 4 groups x 2 bufs x 16KB B slices; reused: u32 cand table
#define OFF_ZF  147456    // 8 warps x 2KB fp32 z-row staging
#define OFF_PN  229376    // 512 f32
#define OFF_ZN  231424    // 96 f32
#define SMEM_SZ 231808

typedef unsigned long long ull;

static __device__ __align__(128) __nv_bfloat16 g_pb[KC * DDIM];
static __device__ float g_pn[KC];

__device__ __forceinline__ uint32_t smem_u32(const void* p) {
    uint32_t a;
    asm("{ .reg .u64 t; cvta.to.shared.u64 t, %1; cvt.u32.u64 %0, t; }" : "=r"(a) : "l"(p));
    return a;
}
__device__ __forceinline__ unsigned fenc(float f) {
    unsigned b = __float_as_uint(f);
    return (b & 0x80000000u) ? ~b : (b | 0x80000000u);
}
__device__ __forceinline__ uint32_t bf2(float a, float b) {
    __nv_bfloat162 h = __floats2bfloat162_rn(a, b);
    return *reinterpret_cast<uint32_t*>(&h);
}
__device__ __forceinline__ void ldsm_x4(uint32_t* r, uint32_t addr) {
    asm volatile("ldmatrix.sync.aligned.m8n8.x4.shared.b16 {%0,%1,%2,%3}, [%4];"
        : "=r"(r[0]), "=r"(r[1]), "=r"(r[2]), "=r"(r[3]) : "r"(addr));
}
__device__ __forceinline__ void mma_bf16(float* c, const uint32_t* a, uint32_t b0, uint32_t b1) {
    asm volatile("mma.sync.aligned.m16n8k16.row.col.f32.bf16.bf16.f32 "
        "{%0,%1,%2,%3}, {%4,%5,%6,%7}, {%8,%9}, {%0,%1,%2,%3};"
        : "+f"(c[0]), "+f"(c[1]), "+f"(c[2]), "+f"(c[3])
        : "r"(a[0]), "r"(a[1]), "r"(a[2]), "r"(a[3]), "r"(b0), "r"(b1));
}
#define CP_COMMIT() asm volatile("cp.async.commit_group;" ::: "memory")
#define GBAR(g) asm volatile("bar.sync %0, 64;" :: "r"((g) + 1) : "memory")

// ---------------- P prep: bf16 copy + norms ----------------
__global__ void p_prep(const float* __restrict__ P) {
    int row = blockIdx.x * 8 + (threadIdx.x >> 5);
    if (row >= KC) return;
    int lane = threadIdx.x & 31;
    const float4* pr = reinterpret_cast<const float4*>(P) + (size_t)row * 128;
    uint2* pb = reinterpret_cast<uint2*>(g_pb) + (size_t)row * 128;
    float s = 0.f;
#pragma unroll
    for (int i = 0; i < 4; ++i) {
        float4 v = pr[lane + 32 * i];
        s += v.x * v.x + v.y * v.y + v.z * v.z + v.w * v.w;
        uint2 o; o.x = bf2(v.x, v.y); o.y = bf2(v.z, v.w);
        pb[lane + 32 * i] = o;
    }
#pragma unroll
    for (int o = 16; o; o >>= 1) s += __shfl_xor_sync(0xffffffffu, s, o);
    if (lane == 0) g_pn[row] = s;
}

// ---- group-local B slice loader: 64 cols x 128 k = 16KB (64 threads/group) ----
__device__ __forceinline__ void load_chunk(uint32_t sb, int i, int g, int gt) {
    const int ct = i >> 2, kp = i & 3, buf = i & 1;
    const uint32_t dst0 = sb + OFF_PS + (uint32_t)g * 32768 + (uint32_t)buf * 16384;
#pragma unroll
    for (int u = gt; u < 1024; u += 64) {
        int n = u >> 4, c = u & 15;
        const __nv_bfloat16* src = g_pb
            + (size_t)(ct * 256 + g * 64 + n) * DDIM + kp * 128 + c * 8;
        uint32_t d = dst0 + (uint32_t)n * 256 + (uint32_t)((c ^ (n & 7)) << 4);
        asm volatile("cp.async.cg.shared.global [%0], [%1], 16;"
                     :: "r"(d), "l"((const void*)src) : "memory");
    }
}

// ---- fused main kernel: 256 threads, 8 warps = 2 m-warps x 4 n-groups, 48x64 tiles ----
__global__ void __launch_bounds__(256, 1) vq_main(
    const float* __restrict__ z, const float* __restrict__ Pf,
    float* __restrict__ zhat, float* __restrict__ ztil, float* __restrict__ idxf)
{
    extern __shared__ char smem[];
    const uint32_t sb = smem_u32(smem);
    const int tid = threadIdx.x, wid = tid >> 5, lane = tid & 31;
    const int row0 = blockIdx.x * TMR;
    const int g = wid >> 1;              // n-group 0..3 (2 warps, 64 threads each)
    const int m_idx = wid & 1;           // m-warp 0..1
    const int m0 = m_idx * 48;
    const int gt = tid & 63;             // 0..63 within group
    const int n0 = g * 64;

    float* s_pn = reinterpret_cast<float*>(smem + OFF_PN);
    float* s_zn = reinterpret_cast<float*>(smem + OFF_ZN);

    // prefetch first B chunk (group-local) before the z prologue
    load_chunk(sb, 0, g, gt);
    CP_COMMIT();

    for (int i = tid; i < KC; i += 256) s_pn[i] = g_pn[i];

    // prologue: z -> bf16 smem (swizzled) + norms; 384 row-quads over 256 threads
    for (int rq = tid; rq < 512; rq += 256) {
        const int r = rq >> 2, q = rq & 3;
        const int rc = min(r, TMR - 1);                // clamp (redundant, benign)
        const int zrow = min(row0 + rc, NROWS - 1);
        const float4* zr = reinterpret_cast<const float4*>(z)
                         + (size_t)zrow * 128 + q * 32;
        float s = 0.f;
#pragma unroll 4
        for (int c = 0; c < 16; ++c) {
            float4 v0 = zr[c * 2], v1 = zr[c * 2 + 1];
            s += v0.x * v0.x + v0.y * v0.y + v0.z * v0.z + v0.w * v0.w;
            s += v1.x * v1.x + v1.y * v1.y + v1.z * v1.z + v1.w * v1.w;
            uint4 o;
            o.x = bf2(v0.x, v0.y); o.y = bf2(v0.z, v0.w);
            o.z = bf2(v1.x, v1.y); o.w = bf2(v1.z, v1.w);
            int chunk = (q * 16 + c) ^ (rc & 7);
            *reinterpret_cast<uint4*>(smem + OFF_ZS + rc * 1024 + chunk * 16) = o;
        }
        s += __shfl_xor_sync(0xffffffffu, s, 1);
        s += __shfl_xor_sync(0xffffffffu, s, 2);
        if (q == 0 && r < TMR) s_zn[r] = s;
    }
    __syncthreads();       // z tile + norms visible to all

    // XOR-foldable LDSM base offsets (addr(kk) = sb + (base ^ (kk<<5)))
    const int ln4 = lane >> 4;
    uint32_t aOff[3];
#pragma unroll
    for (int mt = 0; mt < 3; ++mt) {
        int rg = m0 + mt * 16 + (lane & 15);
        aOff[mt] = (uint32_t)(OFF_ZS + rg * 1024 + ((ln4 ^ (rg & 7)) << 4));
    }
    uint32_t bTerm[4];
    {
        const int b3 = (lane >> 3) & 1;
#pragma unroll
        for (int ntp = 0; ntp < 4; ++ntp) {
            int nl = ntp * 16 + (ln4 << 3) + (lane & 7);
            bTerm[ntp] = (uint32_t)(nl * 256 + ((b3 ^ (nl & 7)) << 4));
        }
    }

    float acc[3][8][4];
    uint32_t bk[6][4];     // per row-slot top-4 packed keys (truncated fenc(dist)|col)
#pragma unroll
    for (int s = 0; s < 6; ++s)
#pragma unroll
        for (int j = 0; j < 4; ++j) bk[s][j] = 0xFFFFFFFFu;
#pragma unroll
    for (int mt = 0; mt < 3; ++mt)
#pragma unroll
        for (int nt = 0; nt < 8; ++nt)
#pragma unroll
            for (int e = 0; e < 4; ++e) acc[mt][nt][e] = 0.f;

    // main pipeline: 8 chunks = 2 col-passes x 4 k-chunks (k=128), double-buffered
    for (int i = 0; i < 8; ++i) {
        asm volatile("cp.async.wait_group 0;" ::: "memory");
        GBAR(g);
        if (i < 7) { load_chunk(sb, i + 1, g, gt); CP_COMMIT(); }

        const int ct = i >> 2, kp = i & 3;
        const uint32_t pOff = (uint32_t)(OFF_PS + g * 32768 + (i & 1) * 16384);
        uint32_t aB[3];
#pragma unroll
        for (int mt = 0; mt < 3; ++mt) aB[mt] = aOff[mt] + (uint32_t)(kp << 8);
        uint32_t bB[4];
#pragma unroll
        for (int ntp = 0; ntp < 4; ++ntp) bB[ntp] = pOff + bTerm[ntp];

#pragma unroll
        for (int kk = 0; kk < 8; ++kk) {
            const uint32_t kx = (uint32_t)(kk << 5);
            // batch ALL fragment loads before any MMA
            uint32_t a[3][4], rb[4][4];
#pragma unroll
            for (int mt = 0; mt < 3; ++mt) ldsm_x4(a[mt], sb + (aB[mt] ^ kx));
#pragma unroll
            for (int ntp = 0; ntp < 4; ++ntp) ldsm_x4(rb[ntp], sb + (bB[ntp] ^ kx));
#pragma unroll
            for (int ntp = 0; ntp < 4; ++ntp)
#pragma unroll
                for (int mt = 0; mt < 3; ++mt) {
                    mma_bf16(acc[mt][ntp * 2],     a[mt], rb[ntp][0], rb[ntp][1]);
                    mma_bf16(acc[mt][ntp * 2 + 1], a[mt], rb[ntp][2], rb[ntp][3]);
                }
        }

        if (kp == 3) {
            // merge col-pass dists (pn - 2*dot) into top-4 packed u32 keys
            const int ctbase = ct * 256;
#pragma unroll
            for (int mt = 0; mt < 3; ++mt)
#pragma unroll
                for (int half = 0; half < 2; ++half) {
                    const int s = mt * 2 + half;
#pragma unroll
                    for (int nt = 0; nt < 8; ++nt)
#pragma unroll
                        for (int e = 0; e < 2; ++e) {
                            const int col = ctbase + n0 + nt * 8 + (lane & 3) * 2 + e;
                            float d = __fmaf_rn(-2.f, acc[mt][nt][half * 2 + e], s_pn[col]);
                            uint32_t key = (fenc(d) & 0xFFFFFE00u) | (unsigned)col;
                            if (key < bk[s][3]) {
                                bk[s][3] = key;
                                if (bk[s][3] < bk[s][2]) { uint32_t t = bk[s][2]; bk[s][2] = bk[s][3]; bk[s][3] = t; }
                                if (bk[s][2] < bk[s][1]) { uint32_t t = bk[s][1]; bk[s][1] = bk[s][2]; bk[s][2] = t; }
                                if (bk[s][1] < bk[s][0]) { uint32_t t = bk[s][0]; bk[s][0] = bk[s][1]; bk[s][1] = t; }
                            }
                            acc[mt][nt][half * 2 + e] = 0.f;
                        }
                }
        }
    }
    __syncthreads();   // all groups done before cand table overwrites B region

    // dump per-lane top-4 u32 keys: 96 rows x 16 slots x 4
    uint32_t* tab = reinterpret_cast<uint32_t*>(smem + OFF_PS);
    {
        const int slot = g * 4 + (lane & 3);
#pragma unroll
        for (int s = 0; s < 6; ++s) {
            const int mt = s >> 1, half = s & 1;
            const int rloc = m0 + mt * 16 + half * 8 + (lane >> 2);
#pragma unroll
            for (int j = 0; j < 4; ++j)
                tab[(rloc * 16 + slot) * 4 + j] = bk[s][j];
        }
    }
    __syncthreads();

    // per-row: global top-4 of 64 u32 keys -> PARALLEL exact fp32 rescore -> outputs
    const float4* z4 = reinterpret_cast<const float4*>(z);
    const float4* P4 = reinterpret_cast<const float4*>(Pf);
    float4* zh4 = reinterpret_cast<float4*>(zhat);
    float4* zt4 = reinterpret_cast<float4*>(ztil);
    float4* zf = reinterpret_cast<float4*>(smem + OFF_ZF + wid * 2048);

    for (int rr = 0; rr < 12; ++rr) {
        const int r = wid * 12 + rr;
        const int zrow = row0 + r;
        const int zc = min(zrow, NROWS - 1);
        float4 za[4];
#pragma unroll
        for (int q = 0; q < 4; ++q) {
            za[q] = z4[(size_t)zc * 128 + q * 32 + lane];
            zf[q * 32 + lane] = za[q];        // stage fp32 z row for grouped rescore
        }
        const float zn = s_zn[r];
        __syncwarp();

        // extract global top-4 candidate columns (u32 keys, min+invalidate)
        uint32_t k0_ = tab[r * 64 + lane];
        uint32_t k1_ = tab[r * 64 + 32 + lane];
        int cand[4];
#pragma unroll
        for (int it = 0; it < 4; ++it) {
            uint32_t m = k0_ < k1_ ? k0_ : k1_;
#pragma unroll
            for (int o = 16; o; o >>= 1) {
                uint32_t om = __shfl_xor_sync(0xffffffffu, m, o);
                m = om < m ? om : m;
            }
            cand[it] = (int)(m & 511u);
            if (k0_ == m) k0_ = 0xFFFFFFFFu;
            if (k1_ == m) k1_ = 0xFFFFFFFFu;
        }

        // grouped rescore: 8-lane group ci handles candidate ci, exact fp32
        const int ci = lane >> 3, li = lane & 7;
        const int c = cand[ci];
        const float4* pc = P4 + (size_t)c * 128;
        float s_ = 0.f;
#pragma unroll
        for (int q2 = 0; q2 < 16; ++q2) {
            float4 pb = pc[q2 * 8 + li];
            float4 zv = zf[q2 * 8 + li];
            s_ = fmaf(zv.x, pb.x, s_);
            s_ = fmaf(zv.y, pb.y, s_);
            s_ = fmaf(zv.z, pb.z, s_);
            s_ = fmaf(zv.w, pb.w, s_);
        }
        s_ += __shfl_xor_sync(0xffffffffu, s_, 1);
        s_ += __shfl_xor_sync(0xffffffffu, s_, 2);
        s_ += __shfl_xor_sync(0xffffffffu, s_, 4);
        float t = __fadd_rn(zn, s_pn[c]);
        float dist = __fadd_rn(t, -2.0f * s_);
        ull key = ((ull)fenc(dist) << 32) | (unsigned)c;
#pragma unroll
        for (int o = 8; o <= 16; o <<= 1) {
            ull ok = __shfl_xor_sync(0xffffffffu, key, o);
            key = ok < key ? ok : key;
        }
        const int cw = (int)(key & 511ull);

        if (zrow < NROWS) {
#pragma unroll
            for (int q = 0; q < 4; ++q) {
                float4 pv = P4[(size_t)cw * 128 + q * 32 + lane];
                size_t go = (size_t)zrow * 128 + q * 32 + lane;
                float4 hv;
                hv.x = __fadd_rn(__fmul_rn(0.7f, za[q].x), __fmul_rn(0.3f, pv.x));
                hv.y = __fadd_rn(__fmul_rn(0.7f, za[q].y), __fmul_rn(0.3f, pv.y));
                hv.z = __fadd_rn(__fmul_rn(0.7f, za[q].z), __fmul_rn(0.3f, pv.z));
                hv.w = __fadd_rn(__fmul_rn(0.7f, za[q].w), __fmul_rn(0.3f, pv.w));
                zt4[go] = pv;
                zh4[go] = hv;
            }
            if (lane == 0) idxf[zrow] = (float)cw;
        }
        __syncwarp();      // zf consumed before next row overwrites
    }
}

extern "C" void kernel_launch(void* const* d_in, const int* in_sizes, int n_in,
                              void* d_out, int out_size)
{
    const float* z = (const float*)d_in[0];
    const float* P = (const float*)d_in[1];
    int N = in_sizes[0] / DDIM;   // 131072

    float* out  = (float*)d_out;
    float* zhat = out;
    float* ztil = out + (size_t)N * DDIM;
    float* idxf = out + 2 * (size_t)N * DDIM;

    cudaFuncSetAttribute(vq_main, cudaFuncAttributeMaxDynamicSharedMemorySize, SMEM_SZ);

    p_prep<<<KC / 8, 256>>>(P);
    vq_main<<<(N + TMR - 1) / TMR, 256, SMEM_SZ>>>(z, P, zhat, ztil, idxf);
}

// round 16
// speedup vs baseline: 1.1235x; 1.1235x over previous
#include <cuda_runtime.h>
#include <cuda_bf16.h>
#include <cstdint>

#define DDIM 512
#define KC   512
#define TMR  128

// smem layout (bytes)
#define OFF_ZS  0         // 128 rows x 1024B bf16, swizzled
#define OFF_PS  131072    // 4 groups x 2 bufs x 8KB B slices; reused: cand table + zf
#define OFF_PN  196608    // 512 f32
#define OFF_ZN  198656    // 128 f32
#define SMEM_SZ 199168

typedef unsigned long long ull;

static __device__ __align__(128) __nv_bfloat16 g_pb[KC * DDIM];
static __device__ float g_pn[KC];

__device__ __forceinline__ uint32_t smem_u32(const void* p) {
    uint32_t a;
    asm("{ .reg .u64 t; cvta.to.shared.u64 t, %1; cvt.u32.u64 %0, t; }" : "=r"(a) : "l"(p));
    return a;
}
__device__ __forceinline__ unsigned fenc(float f) {
    unsigned b = __float_as_uint(f);
    return (b & 0x80000000u) ? ~b : (b | 0x80000000u);
}
__device__ __forceinline__ uint32_t bf2(float a, float b) {
    __nv_bfloat162 h = __floats2bfloat162_rn(a, b);
    return *reinterpret_cast<uint32_t*>(&h);
}
__device__ __forceinline__ void ldsm_x4(uint32_t* r, uint32_t addr) {
    asm volatile("ldmatrix.sync.aligned.m8n8.x4.shared.b16 {%0,%1,%2,%3}, [%4];"
        : "=r"(r[0]), "=r"(r[1]), "=r"(r[2]), "=r"(r[3]) : "r"(addr));
}
__device__ __forceinline__ void mma_bf16(float* c, const uint32_t* a, uint32_t b0, uint32_t b1) {
    asm volatile("mma.sync.aligned.m16n8k16.row.col.f32.bf16.bf16.f32 "
        "{%0,%1,%2,%3}, {%4,%5,%6,%7}, {%8,%9}, {%0,%1,%2,%3};"
        : "+f"(c[0]), "+f"(c[1]), "+f"(c[2]), "+f"(c[3])
        : "r"(a[0]), "r"(a[1]), "r"(a[2]), "r"(a[3]), "r"(b0), "r"(b1));
}
#define CP_COMMIT() asm volatile("cp.async.commit_group;" ::: "memory")
#define GBAR(g) asm volatile("bar.sync %0, 128;" :: "r"((g) + 1) : "memory")

// ---------------- P prep: bf16 copy + norms ----------------
__global__ void p_prep(const float* __restrict__ P) {
    int row = blockIdx.x * 8 + (threadIdx.x >> 5);
    if (row >= KC) return;
    int lane = threadIdx.x & 31;
    const float4* pr = reinterpret_cast<const float4*>(P) + (size_t)row * 128;
    uint2* pb = reinterpret_cast<uint2*>(g_pb) + (size_t)row * 128;
    float s = 0.f;
#pragma unroll
    for (int i = 0; i < 4; ++i) {
        float4 v = pr[lane + 32 * i];
        s += v.x * v.x + v.y * v.y + v.z * v.z + v.w * v.w;
        uint2 o; o.x = bf2(v.x, v.y); o.y = bf2(v.z, v.w);
        pb[lane + 32 * i] = o;
    }
#pragma unroll
    for (int o = 16; o; o >>= 1) s += __shfl_xor_sync(0xffffffffu, s, o);
    if (lane == 0) g_pn[row] = s;
}

// ---- group-local B slice loader: 64 cols x 64 k = 8KB (128 threads/group) ----
// i = chunk 0..15: ct = i>>3 (col pass), kp = i&7 (k position), buf = i&1
__device__ __forceinline__ void load_chunk(uint32_t sb, int i, int g, int gt) {
    const int ct = i >> 3, kp = i & 7, buf = i & 1;
    const uint32_t dst0 = sb + OFF_PS + (uint32_t)g * 16384 + (uint32_t)buf * 8192;
#pragma unroll
    for (int u = gt; u < 512; u += 128) {
        int n = u >> 3, c = u & 7;     // col 0..63, 16B chunk 0..7 within 128B row
        const __nv_bfloat16* src = g_pb
            + (size_t)(ct * 256 + g * 64 + n) * DDIM + kp * 64 + c * 8;
        uint32_t d = dst0 + (uint32_t)n * 128 + (uint32_t)((c ^ (n & 7)) << 4);
        asm volatile("cp.async.cg.shared.global [%0], [%1], 16;"
                     :: "r"(d), "l"((const void*)src) : "memory");
    }
}

// ---- fused main kernel: 512 threads, 16 warps = 4 m-warps x 4 n-groups, 32x64 tiles ----
__global__ void __launch_bounds__(512, 1) vq_main(
    const float* __restrict__ z, const float* __restrict__ Pf,
    float* __restrict__ zhat, float* __restrict__ ztil, float* __restrict__ idxf)
{
    extern __shared__ char smem[];
    const uint32_t sb = smem_u32(smem);
    const int tid = threadIdx.x, wid = tid >> 5, lane = tid & 31;
    const int row0 = blockIdx.x * TMR;
    const int g = wid >> 2;              // n-group 0..3 (4 warps, 128 contiguous threads)
    const int m_idx = wid & 3;           // m-warp 0..3
    const int m0 = m_idx * 32;
    const int gt = tid & 127;            // 0..127 within group
    const int n0 = g * 64;

    float* s_pn = reinterpret_cast<float*>(smem + OFF_PN);
    float* s_zn = reinterpret_cast<float*>(smem + OFF_ZN);

    // prefetch first B chunk (group-local) before the z prologue
    load_chunk(sb, 0, g, gt);
    CP_COMMIT();

    for (int i = tid; i < KC; i += 512) s_pn[i] = g_pn[i];

    // prologue: z -> bf16 smem (swizzled), fused squared norm (4 threads/row)
    {
        const int r = tid >> 2, q = tid & 3;
        const float4* zr = reinterpret_cast<const float4*>(z)
                         + (size_t)(row0 + r) * 128 + q * 32;
        float s = 0.f;
#pragma unroll 4
        for (int c = 0; c < 16; ++c) {
            float4 v0 = zr[c * 2], v1 = zr[c * 2 + 1];
            s += v0.x * v0.x + v0.y * v0.y + v0.z * v0.z + v0.w * v0.w;
            s += v1.x * v1.x + v1.y * v1.y + v1.z * v1.z + v1.w * v1.w;
            uint4 o;
            o.x = bf2(v0.x, v0.y); o.y = bf2(v0.z, v0.w);
            o.z = bf2(v1.x, v1.y); o.w = bf2(v1.z, v1.w);
            int chunk = (q * 16 + c) ^ (r & 7);
            *reinterpret_cast<uint4*>(smem + OFF_ZS + r * 1024 + chunk * 16) = o;
        }
        s += __shfl_xor_sync(0xffffffffu, s, 1);
        s += __shfl_xor_sync(0xffffffffu, s, 2);
        if (q == 0) s_zn[r] = s;
    }
    __syncthreads();       // z tile + norms visible to all

    // XOR-foldable LDSM base offsets (addr(kk) = sb + (base ^ (kk<<5)), kk in 0..3)
    const int ln4 = lane >> 4;
    uint32_t aOff[2];
#pragma unroll
    for (int mt = 0; mt < 2; ++mt) {
        int rg = m0 + mt * 16 + (lane & 15);
        aOff[mt] = (uint32_t)(OFF_ZS + rg * 1024 + ((ln4 ^ (rg & 7)) << 4));
    }
    uint32_t bTerm[4];
    {
        const int b3 = (lane >> 3) & 1;
#pragma unroll
        for (int ntp = 0; ntp < 4; ++ntp) {
            int nl = ntp * 16 + (ln4 << 3) + (lane & 7);
            bTerm[ntp] = (uint32_t)(nl * 128 + ((b3 ^ (nl & 7)) << 4));
        }
    }

    float acc[2][8][4];
    uint32_t bk[4][4];     // per row-slot top-4 packed keys (truncated fenc(dist)|col)
#pragma unroll
    for (int s = 0; s < 4; ++s)
#pragma unroll
        for (int j = 0; j < 4; ++j) bk[s][j] = 0xFFFFFFFFu;
#pragma unroll
    for (int mt = 0; mt < 2; ++mt)
#pragma unroll
        for (int nt = 0; nt < 8; ++nt)
#pragma unroll
            for (int e = 0; e < 4; ++e) acc[mt][nt][e] = 0.f;

    // main pipeline: 16 chunks = 2 col-passes x 8 k-chunks (k=64), double-buffered
    for (int i = 0; i < 16; ++i) {
        asm volatile("cp.async.wait_group 0;" ::: "memory");
        GBAR(g);
        if (i < 15) { load_chunk(sb, i + 1, g, gt); CP_COMMIT(); }

        const int ct = i >> 3, kp = i & 7;
        const uint32_t pOff = (uint32_t)(OFF_PS + g * 16384 + (i & 1) * 8192);
        uint32_t aB0 = aOff[0] + (uint32_t)(kp << 7);
        uint32_t aB1 = aOff[1] + (uint32_t)(kp << 7);
        uint32_t bB[4];
#pragma unroll
        for (int ntp = 0; ntp < 4; ++ntp) bB[ntp] = pOff + bTerm[ntp];

#pragma unroll
        for (int kk = 0; kk < 4; ++kk) {
            const uint32_t kx = (uint32_t)(kk << 5);
            // batch ALL fragment loads before any MMA
            uint32_t a[2][4], rb[4][4];
            ldsm_x4(a[0], sb + (aB0 ^ kx));
            ldsm_x4(a[1], sb + (aB1 ^ kx));
#pragma unroll
            for (int ntp = 0; ntp < 4; ++ntp)
                ldsm_x4(rb[ntp], sb + (bB[ntp] ^ kx));
#pragma unroll
            for (int ntp = 0; ntp < 4; ++ntp)
#pragma unroll
                for (int mt = 0; mt < 2; ++mt) {
                    mma_bf16(acc[mt][ntp * 2],     a[mt], rb[ntp][0], rb[ntp][1]);
                    mma_bf16(acc[mt][ntp * 2 + 1], a[mt], rb[ntp][2], rb[ntp][3]);
                }
        }

        if (kp == 7) {
            // merge col-pass dists (pn - 2*dot) into top-4 packed u32 keys
            const int ctbase = ct * 256;
#pragma unroll
            for (int mt = 0; mt < 2; ++mt)
#pragma unroll
                for (int half = 0; half < 2; ++half) {
                    const int s = mt * 2 + half;
#pragma unroll
                    for (int nt = 0; nt < 8; ++nt)
#pragma unroll
                        for (int e = 0; e < 2; ++e) {
                            const int col = ctbase + n0 + nt * 8 + (lane & 3) * 2 + e;
                            float d = __fmaf_rn(-2.f, acc[mt][nt][half * 2 + e], s_pn[col]);
                            uint32_t key = (fenc(d) & 0xFFFFFE00u) | (unsigned)col;
                            if (key < bk[s][3]) {
                                bk[s][3] = key;
                                if (bk[s][3] < bk[s][2]) { uint32_t t = bk[s][2]; bk[s][2] = bk[s][3]; bk[s][3] = t; }
                                if (bk[s][2] < bk[s][1]) { uint32_t t = bk[s][1]; bk[s][1] = bk[s][2]; bk[s][2] = t; }
                                if (bk[s][1] < bk[s][0]) { uint32_t t = bk[s][0]; bk[s][0] = bk[s][1]; bk[s][1] = t; }
                            }
                            acc[mt][nt][half * 2 + e] = 0.f;
                        }
                }
        }
    }
    __syncthreads();   // all groups done before cand table overwrites B region

    // dump per-lane top-4 u32 keys: 128 rows x 16 slots x 4 (32KB)
    uint32_t* tab = reinterpret_cast<uint32_t*>(smem + OFF_PS);
    {
        const int slot = g * 4 + (lane & 3);
#pragma unroll
        for (int s = 0; s < 4; ++s) {
            const int mt = s >> 1, half = s & 1;
            const int rloc = m0 + mt * 16 + half * 8 + (lane >> 2);
#pragma unroll
            for (int j = 0; j < 4; ++j)
                tab[(rloc * 16 + slot) * 4 + j] = bk[s][j];
        }
    }
    __syncthreads();

    // per-row: global top-4 of 64 u32 keys -> PARALLEL exact fp32 rescore -> outputs
    const float4* z4 = reinterpret_cast<const float4*>(z);
    const float4* P4 = reinterpret_cast<const float4*>(Pf);
    float4* zh4 = reinterpret_cast<float4*>(zhat);
    float4* zt4 = reinterpret_cast<float4*>(ztil);
    float4* zf = reinterpret_cast<float4*>(smem + OFF_PS + 32768 + wid * 2048);

    for (int rr = 0; rr < 8; ++rr) {
        const int r = wid * 8 + rr;
        const int zrow = row0 + r;
        float4 za[4];
#pragma unroll
        for (int q = 0; q < 4; ++q) {
            za[q] = z4[(size_t)zrow * 128 + q * 32 + lane];
            zf[q * 32 + lane] = za[q];        // stage fp32 z row for grouped rescore
        }
        const float zn = s_zn[r];
        __syncwarp();

        // extract global top-4 candidate columns (u32 keys, min+invalidate)
        uint32_t k0_ = tab[r * 64 + lane];
        uint32_t k1_ = tab[r * 64 + 32 + lane];
        int cand[4];
#pragma unroll
        for (int it = 0; it < 4; ++it) {
            uint32_t m = k0_ < k1_ ? k0_ : k1_;
#pragma unroll
            for (int o = 16; o; o >>= 1) {
                uint32_t om = __shfl_xor_sync(0xffffffffu, m, o);
                m = om < m ? om : m;
            }
            cand[it] = (int)(m & 511u);
            if (k0_ == m) k0_ = 0xFFFFFFFFu;
            if (k1_ == m) k1_ = 0xFFFFFFFFu;
        }

        // grouped rescore: 8-lane group ci handles candidate ci, exact fp32
        const int ci = lane >> 3, li = lane & 7;
        const int c = cand[ci];
        const float4* pc = P4 + (size_t)c * 128;
        float s_ = 0.f;
#pragma unroll
        for (int q2 = 0; q2 < 16; ++q2) {
            float4 pb = pc[q2 * 8 + li];
            float4 zv = zf[q2 * 8 + li];
            s_ = fmaf(zv.x, pb.x, s_);
            s_ = fmaf(zv.y, pb.y, s_);
            s_ = fmaf(zv.z, pb.z, s_);
            s_ = fmaf(zv.w, pb.w, s_);
        }
        s_ += __shfl_xor_sync(0xffffffffu, s_, 1);
        s_ += __shfl_xor_sync(0xffffffffu, s_, 2);
        s_ += __shfl_xor_sync(0xffffffffu, s_, 4);
        float t = __fadd_rn(zn, s_pn[c]);
        float dist = __fadd_rn(t, -2.0f * s_);
        ull key = ((ull)fenc(dist) << 32) | (unsigned)c;
#pragma unroll
        for (int o = 8; o <= 16; o <<= 1) {
            ull ok = __shfl_xor_sync(0xffffffffu, key, o);
            key = ok < key ? ok : key;
        }
        const int cw = (int)(key & 511ull);

#pragma unroll
        for (int q = 0; q < 4; ++q) {
            float4 pv = P4[(size_t)cw * 128 + q * 32 + lane];
            size_t go = (size_t)zrow * 128 + q * 32 + lane;
            float4 hv;
            hv.x = __fadd_rn(__fmul_rn(0.7f, za[q].x), __fmul_rn(0.3f, pv.x));
            hv.y = __fadd_rn(__fmul_rn(0.7f, za[q].y), __fmul_rn(0.3f, pv.y));
            hv.z = __fadd_rn(__fmul_rn(0.7f, za[q].z), __fmul_rn(0.3f, pv.z));
            hv.w = __fadd_rn(__fmul_rn(0.7f, za[q].w), __fmul_rn(0.3f, pv.w));
            zt4[go] = pv;
            zh4[go] = hv;
        }
        if (lane == 0) idxf[zrow] = (float)cw;
        __syncwarp();      // zf consumed before next row overwrites
    }
}

extern "C" void kernel_launch(void* const* d_in, const int* in_sizes, int n_in,
                              void* d_out, int out_size)
{
    const float* z = (const float*)d_in[0];
    const float* P = (const float*)d_in[1];
    int N = in_sizes[0] / DDIM;   // 131072

    float* out  = (float*)d_out;
    float* zhat = out;
    float* ztil = out + (size_t)N * DDIM;
    float* idxf = out + 2 * (size_t)N * DDIM;

    cudaFuncSetAttribute(vq_main, cudaFuncAttributeMaxDynamicSharedMemorySize, SMEM_SZ);

    p_prep<<<KC / 8, 256>>>(P);
    vq_main<<<N / TMR, 512, SMEM_SZ>>>(z, P, zhat, ztil, idxf);
}